// round 1
// baseline (speedup 1.0000x reference)
#include <cuda_runtime.h>
#include <cstdint>

#define BATCH 1024
#define INF   512
#define OUTF  512
#define BT    64
#define OT    64
#define KT    16
#define NSTAGES (INF / KT)   // 32

// Scratch (static __device__ globals: allocation-free per harness rules)
__device__ float4 g_P[OUTF * INF];      // {inv_s, -t/s, wavelet_w, base_w}
__device__ float  g_Xx[INF * BATCH];    // x transposed [i][b]
__device__ float  g_Xs[INF * BATCH];    // silu(x) transposed [i][b]

// ---------------------------------------------------------------------------
// Prep 1: pack per-(o,i) parameters into one float4 (amortize reciprocal)
// ---------------------------------------------------------------------------
__global__ void prep_params(const float* __restrict__ bw, const float* __restrict__ ww,
                            const float* __restrict__ sc, const float* __restrict__ tr) {
    int idx = blockIdx.x * blockDim.x + threadIdx.x;
    if (idx >= OUTF * INF) return;
    float s   = sc[idx];
    float inv = __frcp_rn(s);        // correctly-rounded reciprocal
    float4 p;
    p.x = inv;
    p.y = -tr[idx] * inv;            // u = fma(x, inv, -t*inv)
    p.z = ww[idx];
    p.w = bw[idx];
    g_P[idx] = p;
}

// ---------------------------------------------------------------------------
// Prep 2: transpose x to [i][b] and precompute silu(x)
// ---------------------------------------------------------------------------
__global__ void prep_x(const float* __restrict__ x) {
    int idx = blockIdx.x * blockDim.x + threadIdx.x;
    if (idx >= INF * BATCH) return;
    int i = idx / BATCH;
    int b = idx % BATCH;
    float v = x[(size_t)b * INF + i];
    float e = __expf(-v);
    g_Xx[idx] = v;
    g_Xs[idx] = v / (1.0f + e);
}

// ---------------------------------------------------------------------------
// Main: 64x64 (b,o) tile per CTA, 256 threads, 4x4 micro-tile per thread,
// K chunks of 16 double-buffered via cp.async. XOR-swizzled param tile.
// ---------------------------------------------------------------------------
__global__ void __launch_bounds__(256)
wkan_main(const float* __restrict__ bias, float* __restrict__ out) {
    __shared__ float4 sP[2][KT][OT];        // 32 KB  (param tile, swizzled cols)
    __shared__ float4 sX[2][KT][BT / 4];    //  8 KB  (x tile)
    __shared__ float4 sS[2][KT][BT / 4];    //  8 KB  (silu tile)   -> 48 KB total

    const int tid = threadIdx.x;
    const int tb  = tid & 15;        // 16 batch groups
    const int to  = tid >> 4;        // 16 out groups
    const int b0  = blockIdx.x * BT;
    const int o0  = blockIdx.y * OT;

    auto load_stage = [&](int s, int buf) {
        const int k0 = s * KT;
        // ---- param tile: 1024 float4, 4 per thread, coalesced 16B chunks ----
        #pragma unroll
        for (int j = 0; j < 4; ++j) {
            int idx = j * 256 + tid;
            int k   = idx & 15;
            int o   = idx >> 4;
            const float4* src = &g_P[(size_t)(o0 + o) * INF + (k0 + k)];
            uint32_t dst = (uint32_t)__cvta_generic_to_shared(&sP[buf][k][o ^ (k & 7)]);
            asm volatile("cp.async.cg.shared.global [%0], [%1], 16;\n" :: "r"(dst), "l"(src));
        }
        // ---- x / silu tiles: 256 float4 each, 1 per thread ----
        {
            int k  = tid >> 4;
            int b4 = tid & 15;
            const float* srcx = &g_Xx[(size_t)(k0 + k) * BATCH + b0 + b4 * 4];
            uint32_t dstx = (uint32_t)__cvta_generic_to_shared(&sX[buf][k][b4]);
            asm volatile("cp.async.cg.shared.global [%0], [%1], 16;\n" :: "r"(dstx), "l"(srcx));
            const float* srcs = &g_Xs[(size_t)(k0 + k) * BATCH + b0 + b4 * 4];
            uint32_t dsts = (uint32_t)__cvta_generic_to_shared(&sS[buf][k][b4]);
            asm volatile("cp.async.cg.shared.global [%0], [%1], 16;\n" :: "r"(dsts), "l"(srcs));
        }
        asm volatile("cp.async.commit_group;\n" ::);
    };

    float acc[4][4];
    #pragma unroll
    for (int i = 0; i < 4; ++i)
        #pragma unroll
        for (int j = 0; j < 4; ++j) acc[i][j] = 0.0f;

    load_stage(0, 0);
    load_stage(1, 1);

    #pragma unroll 1
    for (int s = 0; s < NSTAGES; ++s) {
        asm volatile("cp.async.wait_group 1;\n" ::);
        __syncthreads();
        const int buf = s & 1;

        #pragma unroll 8
        for (int k = 0; k < KT; ++k) {
            float4 xa = sX[buf][k][tb];
            float4 xs = sS[buf][k][tb];
            float xv[4] = {xa.x, xa.y, xa.z, xa.w};
            float sv[4] = {xs.x, xs.y, xs.z, xs.w};
            #pragma unroll
            for (int oo = 0; oo < 4; ++oo) {
                float4 p = sP[buf][k][(4 * to + oo) ^ (k & 7)];
                #pragma unroll
                for (int bb = 0; bb < 4; ++bb) {
                    float u  = fmaf(xv[bb], p.x, p.y);      // (x - t)/s
                    float u2 = u * u;
                    float e;
                    // exp(-0.5*u^2) = 2^(-u^2 * log2(e)/2)
                    asm("ex2.approx.ftz.f32 %0, %1;" : "=f"(e) : "f"(u2 * -0.72134752044448170f));
                    acc[bb][oo] = fmaf((u2 - 1.0f) * e, p.z, acc[bb][oo]); // wavelet branch
                    acc[bb][oo] = fmaf(sv[bb],          p.w, acc[bb][oo]); // base branch (fused)
                }
            }
        }
        __syncthreads();
        if (s + 2 < NSTAGES) load_stage(s + 2, buf);
        else                 asm volatile("cp.async.commit_group;\n" ::);  // keep group count invariant
    }

    // Epilogue: add bias, vectorized store
    float4 bv = *reinterpret_cast<const float4*>(bias + o0 + 4 * to);
    #pragma unroll
    for (int bb = 0; bb < 4; ++bb) {
        int b = b0 + 4 * tb + bb;
        float4 r;
        r.x = acc[bb][0] + bv.x;
        r.y = acc[bb][1] + bv.y;
        r.z = acc[bb][2] + bv.z;
        r.w = acc[bb][3] + bv.w;
        *reinterpret_cast<float4*>(out + (size_t)b * OUTF + o0 + 4 * to) = r;
    }
}

// ---------------------------------------------------------------------------
extern "C" void kernel_launch(void* const* d_in, const int* in_sizes, int n_in,
                              void* d_out, int out_size) {
    (void)in_sizes; (void)n_in; (void)out_size;
    const float* x    = (const float*)d_in[0];
    const float* bw   = (const float*)d_in[1];
    const float* ww   = (const float*)d_in[2];
    const float* sc   = (const float*)d_in[3];
    const float* tr   = (const float*)d_in[4];
    const float* bias = (const float*)d_in[5];
    float* out = (float*)d_out;

    prep_params<<<(OUTF * INF + 255) / 256, 256>>>(bw, ww, sc, tr);
    prep_x<<<(INF * BATCH + 255) / 256, 256>>>(x);
    wkan_main<<<dim3(BATCH / BT, OUTF / OT), 256>>>(bias, out);
}